// round 15
// baseline (speedup 1.0000x reference)
#include <cuda_runtime.h>
#include <cuda_fp16.h>
#include <cstdint>
#include <math.h>

#define BATCH 4
#define C64   64
#define CR    32
#define HIMG  96
#define SIMG  48
#define NQ    9216      // 96*96 queries
#define NL    2304      // 48*48 keys
#define DK    288       // 32*3*3
#define DV    576       // 64*3*3
#define OHW   191
#define SCALEF 10.0f
#define EPSF   1e-4f

// ---------------- scratch (device globals; no allocation allowed) ----------------
__device__ float  g_match[(size_t)BATCH * CR  * NQ];
__device__ float  g_embed[(size_t)BATCH * C64 * NL];
__device__ float  g_ref  [(size_t)BATCH * CR  * NL];
__device__ __half g_Q    [(size_t)BATCH * NQ  * DK];
__device__ __half g_Km   [(size_t)BATCH * NL  * DK];
__device__ __half g_V    [(size_t)BATCH * DV  * NL];
__device__ float  g_invn [(size_t)BATCH * NL];
__device__ float  g_S    [(size_t)BATCH * NQ  * NL];   // fp32 logits
__device__ __half g_P    [(size_t)BATCH * NQ  * NL];   // fp16 probs
__device__ float  g_O    [(size_t)BATCH * NQ  * DV];

// ==================== FP16 tensor-core GEMM (96x144 block, 48x48 warp tiles) =====
// C[M,Nb] = alpha * A[M,K] * B[Nb,K]^T ; A,B fp16 K-contig, C fp32.
// 6 warps (2m x 3n) of 48x48; 192 threads; 3 CTAs/SM (18 warps) via launch_bounds.
// K-tile 32, 3-stage cp.async, one __syncthreads per K-tile.
// REQUIRES: M % 96 == 0, Nb % 144 == 0, K % 32 == 0 (no guards anywhere).
// Smem rows padded to 80B -> ldmatrix 8-row phases hit banks 20r%32, all distinct.

#define GB_THR   192
#define GB_A_ST  (96 * 80)               // 7680 B
#define GB_STAGE ((96 + 144) * 80)       // 19200 B
#define GB_SMEM  (3 * GB_STAGE)          // 57600 B -> 3 CTAs/SM

__device__ __forceinline__ void mma_f16(float c[4], const uint32_t a[4], const uint32_t b[2]) {
    asm volatile(
        "mma.sync.aligned.m16n8k16.row.col.f32.f16.f16.f32 "
        "{%0,%1,%2,%3}, {%4,%5,%6,%7}, {%8,%9}, {%0,%1,%2,%3};"
        : "+f"(c[0]), "+f"(c[1]), "+f"(c[2]), "+f"(c[3])
        : "r"(a[0]), "r"(a[1]), "r"(a[2]), "r"(a[3]), "r"(b[0]), "r"(b[1]));
}

#define LDSM_X4(r0, r1, r2, r3, addr) \
    asm volatile("ldmatrix.sync.aligned.m8n8.x4.shared.b16 {%0,%1,%2,%3}, [%4];" \
                 : "=r"(r0), "=r"(r1), "=r"(r2), "=r"(r3) : "r"(addr))

__device__ __forceinline__ void cp16(uint32_t dst, const void* src) {
    asm volatile("cp.async.cg.shared.global [%0], [%1], 16;" :: "r"(dst), "l"(src));
}

__global__ void __launch_bounds__(GB_THR, 3)
gemm_f16(const __half* __restrict__ A, const __half* __restrict__ B, float* __restrict__ C,
         int K, int Nb, float alpha, size_t sA, size_t sB, size_t sC) {
    extern __shared__ __align__(16) char smc[];
    const uint32_t smem_u = (uint32_t)__cvta_generic_to_shared(smc);

    const int tid = threadIdx.x;
    const int warp = tid >> 5, lane = tid & 31;
    const int g = lane >> 2, t = lane & 3;
    const int wm = warp & 1, wn = warp >> 1;          // 2m x 3n of 48x48
    const int m0 = blockIdx.y * 96, n0 = blockIdx.x * 144;
    const __half* Ab = A + (size_t)blockIdx.z * sA;
    const __half* Bb = B + (size_t)blockIdx.z * sB;
    float* Cb = C + (size_t)blockIdx.z * sC;

    float acc[3][6][4];
#pragma unroll
    for (int i = 0; i < 3; i++)
#pragma unroll
        for (int j = 0; j < 6; j++)
#pragma unroll
            for (int r = 0; r < 4; r++) acc[i][j][r] = 0.f;

    // loader: 384 A-chunks + 576 B-chunks of 16B per stage = 960 = 192*5 exact
    auto ld_stage = [&](int c, int s) {
        const int k0 = c << 5;
        const uint32_t sb = smem_u + (uint32_t)s * GB_STAGE;
#pragma unroll
        for (int i = 0; i < 5; i++) {
            int ch = tid + GB_THR * i;
            if (ch < 384) {
                int row = ch >> 2, c16 = ch & 3;
                cp16(sb + row * 80 + c16 * 16,
                     Ab + (size_t)(m0 + row) * K + k0 + c16 * 8);
            } else {
                int bc = ch - 384;          // < 576
                int row = bc >> 2, c16 = bc & 3;
                cp16(sb + GB_A_ST + row * 80 + c16 * 16,
                     Bb + (size_t)(n0 + row) * K + k0 + c16 * 8);
            }
        }
        asm volatile("cp.async.commit_group;" ::: "memory");
    };

    const int nk = K >> 5;
    ld_stage(0, 0);
    if (nk > 1) ld_stage(1, 1);

    // ldmatrix lane addressing (fragment maps validated rounds 4-14)
    const uint32_t a_row = (uint32_t)(wm * 48 + (lane & 15));          // + mi*16
    const uint32_t a_chk = (uint32_t)(lane >> 4);                      // + ks*2
    const uint32_t b_row = (uint32_t)(wn * 48 + (lane & 7) + ((lane & 16) >> 1)); // + 16*a
    const uint32_t b_chk = (uint32_t)((lane >> 3) & 1);                // + ks*2

    int s = 0, ps = 2;
    for (int kt = 0; kt < nk; kt++) {
        // pending groups: loads kt, kt+1. wait 1 drains kt; last iter drains all.
        if (kt + 1 < nk) asm volatile("cp.async.wait_group 1;" ::: "memory");
        else             asm volatile("cp.async.wait_group 0;" ::: "memory");
        __syncthreads();
        if (kt + 2 < nk) {
            ld_stage(kt + 2, ps);
            ps = (ps == 2) ? 0 : ps + 1;
        }
        const uint32_t As = smem_u + (uint32_t)s * GB_STAGE;
        const uint32_t Bs = As + GB_A_ST;
#pragma unroll
        for (int ks = 0; ks < 2; ks++) {
            uint32_t afr[3][4], bfr[6][2];
#pragma unroll
            for (int mi = 0; mi < 3; mi++) {
                uint32_t ad = As + (a_row + mi * 16) * 80 + (a_chk + ks * 2) * 16;
                LDSM_X4(afr[mi][0], afr[mi][1], afr[mi][2], afr[mi][3], ad);
            }
#pragma unroll
            for (int a = 0; a < 3; a++) {
                uint32_t bd = Bs + (b_row + a * 16) * 80 + (b_chk + ks * 2) * 16;
                LDSM_X4(bfr[2 * a][0], bfr[2 * a][1], bfr[2 * a + 1][0], bfr[2 * a + 1][1], bd);
            }
#pragma unroll
            for (int mi = 0; mi < 3; mi++)
#pragma unroll
                for (int ni = 0; ni < 6; ni++)
                    mma_f16(acc[mi][ni], afr[mi], bfr[ni]);
        }
        s = (s == 2) ? 0 : s + 1;
    }

    // epilogue (no guards: exact tiling)
#pragma unroll
    for (int mi = 0; mi < 3; mi++) {
        int row0 = m0 + wm * 48 + mi * 16 + g;
#pragma unroll
        for (int ni = 0; ni < 6; ni++) {
            int col = n0 + wn * 48 + ni * 8 + 2 * t;
            *(float2*)(Cb + (size_t)row0 * Nb + col) =
                make_float2(acc[mi][ni][0] * alpha, acc[mi][ni][1] * alpha);
            *(float2*)(Cb + (size_t)(row0 + 8) * Nb + col) =
                make_float2(acc[mi][ni][2] * alpha, acc[mi][ni][3] * alpha);
        }
    }
}

// ---------------- fused 1x1 convs + PReLU (one launch, 3 segments) ----------------
template<int COUT>
__device__ __forceinline__ void conv_body(const float* __restrict__ in,
                                          const float* __restrict__ w,
                                          const float* __restrict__ bias,
                                          const float* __restrict__ a,
                                          float* __restrict__ out, int HW, float* ws) {
    for (int i = threadIdx.x; i < COUT * C64; i += 256) ws[i] = w[i];
    __syncthreads();
    const float alpha = a[0];
    int idx = blockIdx.x * 256 + threadIdx.x;          // b*HW + p (grid exact)
    int b = idx / HW, p = idx - b * HW;
    const float* inp = in + (size_t)b * C64 * HW + p;
    float acc[COUT];
#pragma unroll
    for (int o = 0; o < COUT; o++) acc[o] = bias[o];
    for (int c = 0; c < C64; c++) {
        float v = inp[(size_t)c * HW];
#pragma unroll
        for (int o = 0; o < COUT; o++) acc[o] = fmaf(ws[o * C64 + c], v, acc[o]);
    }
    float* op = out + (size_t)b * COUT * HW + p;
#pragma unroll
    for (int o = 0; o < COUT; o++) {
        float v = acc[o];
        op[(size_t)o * HW] = (v >= 0.f) ? v : alpha * v;
    }
}

__global__ void __launch_bounds__(256)
fused_convs(const float* __restrict__ input, const float* __restrict__ small,
            const float* __restrict__ w1, const float* __restrict__ b1, const float* __restrict__ a1,
            const float* __restrict__ w2, const float* __restrict__ b2, const float* __restrict__ a2,
            const float* __restrict__ wa, const float* __restrict__ ba, const float* __restrict__ aa,
            float* __restrict__ pm, float* __restrict__ pe, float* __restrict__ pr) {
    __shared__ float ws[C64 * C64];
    if (blockIdx.y == 0) {
        conv_body<CR>(input, w1, b1, a1, pm, NQ, ws);
    } else if (blockIdx.y == 1) {
        if (blockIdx.x >= 36) return;
        conv_body<C64>(small, wa, ba, aa, pe, NL, ws);
    } else {
        if (blockIdx.x >= 36) return;
        conv_body<CR>(small, w2, b2, a2, pr, NL, ws);
    }
}

// ---------------- per-key inverse patch norms ----------------
__global__ void key_inv_norms() {
    int idx = blockIdx.x * 256 + threadIdx.x;
    int l = idx % NL, b = idx / NL;
    int ly = l / SIMG, lx = l % SIMG;
    const float* rb = g_ref + (size_t)b * CR * NL;
    float ss = 0.f;
    for (int c = 0; c < CR; c++)
        for (int ky = 0; ky < 3; ky++) {
            int yy = ly + ky - 1;
            if (yy < 0 || yy >= SIMG) continue;
            for (int kx = 0; kx < 3; kx++) {
                int xx = lx + kx - 1;
                if (xx < 0 || xx >= SIMG) continue;
                float v = rb[(c * SIMG + yy) * SIMG + xx];
                ss += v * v;
            }
        }
    g_invn[idx] = 1.f / fmaxf(sqrtf(ss), EPSF);
}

// ---------------- fused Q / Km / V materialization (one launch, segmented) ----------------
#define QBLK 10368   // NQ*DK/256
#define KBLK 2592    // NL*DK/256
#define VBLK 5184    // DV*NL/256

__global__ void __launch_bounds__(256)
fused_build() {
    uint32_t b = blockIdx.y;
    uint32_t bx = blockIdx.x;
    if (bx < QBLK) {
        uint32_t idx = bx * 256u + threadIdx.x;            // < NQ*DK
        uint32_t d = idx % DK, q = idx / DK;
        uint32_t c = d / 9, kk = d % 9, ky = kk / 3, kx = kk % 3;
        uint32_t y = q / HIMG, x = q % HIMG;
        int yy = (int)(y + ky) - 1, xx = (int)(x + kx) - 1;
        float v = 0.f;
        if (yy >= 0 && yy < HIMG && xx >= 0 && xx < HIMG)
            v = g_match[(size_t)b * (CR * NQ) + (c * HIMG + yy) * HIMG + xx];
        g_Q[(size_t)b * (NQ * DK) + idx] = __float2half_rn(v);
    } else if (bx < QBLK + KBLK) {
        uint32_t idx = (bx - QBLK) * 256u + threadIdx.x;   // < NL*DK
        uint32_t d = idx % DK, l = idx / DK;
        uint32_t c = d / 9, kk = d % 9, ky = kk / 3, kx = kk % 3;
        uint32_t ly = l / SIMG, lx = l % SIMG;
        int yy = (int)(ly + ky) - 1, xx = (int)(lx + kx) - 1;
        float v = 0.f;
        if (yy >= 0 && yy < SIMG && xx >= 0 && xx < SIMG)
            v = g_ref[(size_t)b * (CR * NL) + (c * SIMG + yy) * SIMG + xx];
        g_Km[(size_t)b * (NL * DK) + idx] = __float2half_rn(v * g_invn[b * NL + l]);
    } else {
        uint32_t idx = (bx - QBLK - KBLK) * 256u + threadIdx.x;  // < DV*NL
        uint32_t l = idx % NL, dv = idx / NL;
        uint32_t c = dv / 9, kk = dv % 9, ky = kk / 3, kx = kk % 3;
        uint32_t ly = l / SIMG, lx = l % SIMG;
        int yy = (int)(ly + ky) - 1, xx = (int)(lx + kx) - 1;
        float v = 0.f;
        if (yy >= 0 && yy < SIMG && xx >= 0 && xx < SIMG)
            v = g_embed[(size_t)b * (C64 * NL) + (c * SIMG + yy) * SIMG + xx];
        g_V[(size_t)b * (DV * NL) + idx] = __float2half_rn(v);
    }
}

// ---------------- row softmax over 2304 keys: fp32 S -> fp16 P ----------------
// Warp-shuffle reductions: 3 syncthreads total.
__global__ void __launch_bounds__(256)
softmax_rows() {
    const float* p = g_S + (size_t)blockIdx.x * NL;
    __half* po = g_P + (size_t)blockIdx.x * NL;
    const int t = threadIdx.x;
    const int wid = t >> 5, lane = t & 31;
    __shared__ float red[8];

    float v[9];
    float m = -1e30f;
#pragma unroll
    for (int i = 0; i < 9; i++) { v[i] = p[t + i * 256]; m = fmaxf(m, v[i]); }
#pragma unroll
    for (int o = 16; o > 0; o >>= 1) m = fmaxf(m, __shfl_xor_sync(0xffffffffu, m, o));
    if (lane == 0) red[wid] = m;
    __syncthreads();
#pragma unroll
    for (int w = 0; w < 8; w++) m = fmaxf(m, red[w]);

    float sum = 0.f;
#pragma unroll
    for (int i = 0; i < 9; i++) { v[i] = __expf(v[i] - m); sum += v[i]; }
#pragma unroll
    for (int o = 16; o > 0; o >>= 1) sum += __shfl_xor_sync(0xffffffffu, sum, o);
    __syncthreads();                       // red[] reuse: all reads of max done
    if (lane == 0) red[wid] = sum;
    __syncthreads();
    sum = 0.f;
#pragma unroll
    for (int w = 0; w < 8; w++) sum += red[w];
    float inv = 1.f / sum;
#pragma unroll
    for (int i = 0; i < 9; i++) po[t + i * 256] = __float2half_rn(v[i] * inv);
}

// ---------------- gather epilogue (stride-2 transposed conv as gather) ----------------
__global__ void __launch_bounds__(256)
epilogue(float* __restrict__ out) {
    uint32_t idx = blockIdx.x * 256u + threadIdx.x;   // per-batch C64*OHW*OHW
    uint32_t b = blockIdx.y;
    if (idx >= (uint32_t)C64 * OHW * OHW) return;
    uint32_t X = idx % OHW;
    uint32_t r = idx / OHW;
    uint32_t Y = r % OHW;
    uint32_t c = r / OHW;

    int ys[2], kys[2], ny;
    if (Y & 1) { ny = 2; ys[0] = (Y - 1) >> 1; kys[0] = 2; ys[1] = (Y + 1) >> 1; kys[1] = 0; }
    else       { ny = 1; ys[0] = Y >> 1;       kys[0] = 1; }
    int xs[2], kxs[2], nx;
    if (X & 1) { nx = 2; xs[0] = (X - 1) >> 1; kxs[0] = 2; xs[1] = (X + 1) >> 1; kxs[1] = 0; }
    else       { nx = 1; xs[0] = X >> 1;       kxs[0] = 1; }

    const float* Ob = g_O + (size_t)b * NQ * DV;
    float sv = 0.f;
    for (int iy = 0; iy < ny; iy++)
        for (int ix = 0; ix < nx; ix++) {
            uint32_t q = ys[iy] * HIMG + xs[ix];
            sv += Ob[q * DV + c * 9 + kys[iy] * 3 + kxs[ix]];
        }
    out[(size_t)b * (C64 * OHW * OHW) + idx] = sv * (1.0f / 6.0f);
}

// ---------------- launch ----------------
extern "C" void kernel_launch(void* const* d_in, const int* in_sizes, int n_in,
                              void* d_out, int out_size) {
    const float* input = (const float*)d_in[0];
    const float* small = (const float*)d_in[1];
    const float* w1 = (const float*)d_in[2];
    const float* b1 = (const float*)d_in[3];
    const float* a1 = (const float*)d_in[4];
    const float* w2 = (const float*)d_in[5];
    const float* b2 = (const float*)d_in[6];
    const float* a2 = (const float*)d_in[7];
    const float* wa = (const float*)d_in[8];
    const float* ba = (const float*)d_in[9];
    const float* aa = (const float*)d_in[10];
    float* out = (float*)d_out;

    float *p_match, *p_embed, *p_ref, *p_S, *p_O;
    __half *p_Q, *p_Km, *p_V, *p_P;
    cudaGetSymbolAddress((void**)&p_match, g_match);
    cudaGetSymbolAddress((void**)&p_embed, g_embed);
    cudaGetSymbolAddress((void**)&p_ref,   g_ref);
    cudaGetSymbolAddress((void**)&p_Q,     g_Q);
    cudaGetSymbolAddress((void**)&p_Km,    g_Km);
    cudaGetSymbolAddress((void**)&p_V,     g_V);
    cudaGetSymbolAddress((void**)&p_S,     g_S);
    cudaGetSymbolAddress((void**)&p_P,     g_P);
    cudaGetSymbolAddress((void**)&p_O,     g_O);

    cudaFuncSetAttribute(gemm_f16, cudaFuncAttributeMaxDynamicSharedMemorySize, GB_SMEM);

    // #0: all three feature maps
    fused_convs<<<dim3(144, 3), 256>>>(input, small, w1, b1, a1, w2, b2, a2, wa, ba, aa,
                                       p_match, p_embed, p_ref);
    // #1: key norms
    key_inv_norms<<<36, 256>>>();
    // #2: Q / Km / V (fp16)
    fused_build<<<dim3(QBLK + KBLK + VBLK, BATCH), 256>>>();
    // #3: S = 10 * Q Km^T   <-- ncu capture target
    gemm_f16<<<dim3(NL / 144, NQ / 96, BATCH), GB_THR, GB_SMEM>>>(
        p_Q, p_Km, p_S, DK, NL, SCALEF,
        (size_t)NQ * DK, (size_t)NL * DK, (size_t)NQ * NL);
    // #4: softmax -> fp16 P
    softmax_rows<<<BATCH * NQ, 256>>>();
    // #5: O = P V
    gemm_f16<<<dim3(DV / 144, NQ / 96, BATCH), GB_THR, GB_SMEM>>>(
        p_P, p_V, p_O, NL, DV, 1.0f,
        (size_t)NQ * NL, (size_t)DV * NL, (size_t)NQ * DV);
    // #6: gather into [4,64,191,191] with /6
    epilogue<<<dim3(9121, BATCH), 256>>>(out);
}

// round 16
// speedup vs baseline: 1.0355x; 1.0355x over previous
#include <cuda_runtime.h>
#include <cuda_fp16.h>
#include <cstdint>
#include <math.h>

#define BATCH 4
#define C64   64
#define CR    32
#define HIMG  96
#define SIMG  48
#define NQ    9216      // 96*96 queries
#define NL    2304      // 48*48 keys
#define DK    288       // 32*3*3
#define DV    576       // 64*3*3
#define OHW   191
#define SCALEF 10.0f
#define EPSF   1e-4f

// ---------------- scratch (device globals; no allocation allowed) ----------------
__device__ float  g_match[(size_t)BATCH * CR  * NQ];
__device__ float  g_embed[(size_t)BATCH * C64 * NL];
__device__ float  g_ref  [(size_t)BATCH * CR  * NL];
__device__ __half g_Q    [(size_t)BATCH * NQ  * DK];
__device__ __half g_Km   [(size_t)BATCH * NL  * DK];
__device__ __half g_V    [(size_t)BATCH * DV  * NL];
__device__ float  g_invn [(size_t)BATCH * NL];
__device__ float  g_S    [(size_t)BATCH * NQ  * NL];   // fp32 logits
__device__ __half g_P    [(size_t)BATCH * NQ  * NL];   // fp16 probs
__device__ float  g_O    [(size_t)BATCH * NQ  * DV];

// ==================== FP16 tensor-core GEMM (round-14 proven config) ====================
// C[M,Nb] = alpha * A[M,K] * B[Nb,K]^T ; A,B fp16 K-contig, C fp32.
// Template NT in {128, 192}: block tile 128 x NT, NT/16 warps (4m x NT/64 n)
// each 32x64. K-tile 32, 3-stage cp.async, one __syncthreads per K-tile.
// REQUIRES: M % 128 == 0, Nb % NT == 0, K % 32 == 0 (no guards anywhere).
// Smem rows padded to 80B -> ldmatrix 8-row phases hit banks 20r%32, all distinct.

__device__ __forceinline__ void mma_f16(float c[4], const uint32_t a[4], const uint32_t b[2]) {
    asm volatile(
        "mma.sync.aligned.m16n8k16.row.col.f32.f16.f16.f32 "
        "{%0,%1,%2,%3}, {%4,%5,%6,%7}, {%8,%9}, {%0,%1,%2,%3};"
        : "+f"(c[0]), "+f"(c[1]), "+f"(c[2]), "+f"(c[3])
        : "r"(a[0]), "r"(a[1]), "r"(a[2]), "r"(a[3]), "r"(b[0]), "r"(b[1]));
}

#define LDSM_X4(r0, r1, r2, r3, addr) \
    asm volatile("ldmatrix.sync.aligned.m8n8.x4.shared.b16 {%0,%1,%2,%3}, [%4];" \
                 : "=r"(r0), "=r"(r1), "=r"(r2), "=r"(r3) : "r"(addr))

__device__ __forceinline__ void cp16(uint32_t dst, const void* src) {
    asm volatile("cp.async.cg.shared.global [%0], [%1], 16;" :: "r"(dst), "l"(src));
}

template<int NT>
__global__ void __launch_bounds__(NT * 2, 256 / NT)
gemm_f16(const __half* __restrict__ A, const __half* __restrict__ B, float* __restrict__ C,
         int K, int Nb, float alpha, size_t sA, size_t sB, size_t sC) {
    constexpr int NTHR   = NT * 2;
    constexpr int A_ST   = 128 * 80;
    constexpr int STAGE  = (128 + NT) * 80;
    constexpr int A_CH   = 512;
    constexpr int TOT_CH = 512 + NT * 4;

    extern __shared__ __align__(16) char smc[];
    const uint32_t smem_u = (uint32_t)__cvta_generic_to_shared(smc);

    const int tid = threadIdx.x;
    const int warp = tid >> 5, lane = tid & 31;
    const int g = lane >> 2, t = lane & 3;
    const int wm = warp & 3, wn = warp >> 2;
    const int m0 = blockIdx.y * 128, n0 = blockIdx.x * NT;
    const __half* Ab = A + (size_t)blockIdx.z * sA;
    const __half* Bb = B + (size_t)blockIdx.z * sB;
    float* Cb = C + (size_t)blockIdx.z * sC;

    float acc[2][8][4];
#pragma unroll
    for (int i = 0; i < 2; i++)
#pragma unroll
        for (int j = 0; j < 8; j++)
#pragma unroll
            for (int r = 0; r < 4; r++) acc[i][j][r] = 0.f;

    auto ld_stage = [&](int c, int s) {
        const int k0 = c << 5;
        const uint32_t sb = smem_u + (uint32_t)s * STAGE;
#pragma unroll
        for (int i = 0; i < (TOT_CH + NTHR - 1) / NTHR; i++) {
            int ch = tid + NTHR * i;
            if (ch < A_CH) {
                int row = ch >> 2, c16 = ch & 3;
                cp16(sb + row * 80 + c16 * 16,
                     Ab + (size_t)(m0 + row) * K + k0 + c16 * 8);
            } else if (ch < TOT_CH) {
                int bc = ch - A_CH;
                int row = bc >> 2, c16 = bc & 3;
                cp16(sb + A_ST + row * 80 + c16 * 16,
                     Bb + (size_t)(n0 + row) * K + k0 + c16 * 8);
            }
        }
        asm volatile("cp.async.commit_group;" ::: "memory");
    };

    const int nk = K >> 5;
    ld_stage(0, 0);
    if (nk > 1) ld_stage(1, 1);

    const uint32_t a_row = (uint32_t)(wm * 32 + (lane & 15));
    const uint32_t a_chk = (uint32_t)(lane >> 4);
    const uint32_t b_row = (uint32_t)(wn * 64 + (lane & 7) + ((lane & 16) >> 1));
    const uint32_t b_chk = (uint32_t)((lane >> 3) & 1);

    int s = 0, ps = 2;
    for (int kt = 0; kt < nk; kt++) {
        if (kt + 1 < nk) asm volatile("cp.async.wait_group 1;" ::: "memory");
        else             asm volatile("cp.async.wait_group 0;" ::: "memory");
        __syncthreads();
        if (kt + 2 < nk) {
            ld_stage(kt + 2, ps);
            ps = (ps == 2) ? 0 : ps + 1;
        }
        const uint32_t As = smem_u + (uint32_t)s * STAGE;
        const uint32_t Bs = As + A_ST;
#pragma unroll
        for (int ks = 0; ks < 2; ks++) {
            uint32_t afr[2][4], bfr[8][2];
#pragma unroll
            for (int mi = 0; mi < 2; mi++) {
                uint32_t ad = As + (a_row + mi * 16) * 80 + (a_chk + ks * 2) * 16;
                LDSM_X4(afr[mi][0], afr[mi][1], afr[mi][2], afr[mi][3], ad);
            }
#pragma unroll
            for (int a = 0; a < 4; a++) {
                uint32_t bd = Bs + (b_row + a * 16) * 80 + (b_chk + ks * 2) * 16;
                LDSM_X4(bfr[2 * a][0], bfr[2 * a][1], bfr[2 * a + 1][0], bfr[2 * a + 1][1], bd);
            }
#pragma unroll
            for (int mi = 0; mi < 2; mi++)
#pragma unroll
                for (int ni = 0; ni < 8; ni++)
                    mma_f16(acc[mi][ni], afr[mi], bfr[ni]);
        }
        s = (s == 2) ? 0 : s + 1;
    }

#pragma unroll
    for (int mi = 0; mi < 2; mi++) {
        int row0 = m0 + wm * 32 + mi * 16 + g;
#pragma unroll
        for (int ni = 0; ni < 8; ni++) {
            int col = n0 + wn * 64 + ni * 8 + 2 * t;
            *(float2*)(Cb + (size_t)row0 * Nb + col) =
                make_float2(acc[mi][ni][0] * alpha, acc[mi][ni][1] * alpha);
            *(float2*)(Cb + (size_t)(row0 + 8) * Nb + col) =
                make_float2(acc[mi][ni][2] * alpha, acc[mi][ni][3] * alpha);
        }
    }
}

#define G1_SMEM (3 * (128 + 128) * 80)   // 61440
#define G2_SMEM (3 * (128 + 192) * 80)   // 76800

// ---------------- fused 1x1 convs + PReLU (one launch, 3 segments) ----------------
template<int COUT>
__device__ __forceinline__ void conv_body(const float* __restrict__ in,
                                          const float* __restrict__ w,
                                          const float* __restrict__ bias,
                                          const float* __restrict__ a,
                                          float* __restrict__ out, int HW, float* ws) {
    for (int i = threadIdx.x; i < COUT * C64; i += 256) ws[i] = w[i];
    __syncthreads();
    const float alpha = a[0];
    int idx = blockIdx.x * 256 + threadIdx.x;
    int b = idx / HW, p = idx - b * HW;
    const float* inp = in + (size_t)b * C64 * HW + p;
    float acc[COUT];
#pragma unroll
    for (int o = 0; o < COUT; o++) acc[o] = bias[o];
    for (int c = 0; c < C64; c++) {
        float v = inp[(size_t)c * HW];
#pragma unroll
        for (int o = 0; o < COUT; o++) acc[o] = fmaf(ws[o * C64 + c], v, acc[o]);
    }
    float* op = out + (size_t)b * COUT * HW + p;
#pragma unroll
    for (int o = 0; o < COUT; o++) {
        float v = acc[o];
        op[(size_t)o * HW] = (v >= 0.f) ? v : alpha * v;
    }
}

__global__ void __launch_bounds__(256)
fused_convs(const float* __restrict__ input, const float* __restrict__ small,
            const float* __restrict__ w1, const float* __restrict__ b1, const float* __restrict__ a1,
            const float* __restrict__ w2, const float* __restrict__ b2, const float* __restrict__ a2,
            const float* __restrict__ wa, const float* __restrict__ ba, const float* __restrict__ aa,
            float* __restrict__ pm, float* __restrict__ pe, float* __restrict__ pr) {
    __shared__ float ws[C64 * C64];
    if (blockIdx.y == 0) {
        conv_body<CR>(input, w1, b1, a1, pm, NQ, ws);
    } else if (blockIdx.y == 1) {
        if (blockIdx.x >= 36) return;
        conv_body<C64>(small, wa, ba, aa, pe, NL, ws);
    } else {
        if (blockIdx.x >= 36) return;
        conv_body<CR>(small, w2, b2, a2, pr, NL, ws);
    }
}

// ---------------- per-key inverse patch norms ----------------
__global__ void key_inv_norms() {
    int idx = blockIdx.x * 256 + threadIdx.x;
    int l = idx % NL, b = idx / NL;
    int ly = l / SIMG, lx = l % SIMG;
    const float* rb = g_ref + (size_t)b * CR * NL;
    float ss = 0.f;
    for (int c = 0; c < CR; c++)
        for (int ky = 0; ky < 3; ky++) {
            int yy = ly + ky - 1;
            if (yy < 0 || yy >= SIMG) continue;
            for (int kx = 0; kx < 3; kx++) {
                int xx = lx + kx - 1;
                if (xx < 0 || xx >= SIMG) continue;
                float v = rb[(c * SIMG + yy) * SIMG + xx];
                ss += v * v;
            }
        }
    g_invn[idx] = 1.f / fmaxf(sqrtf(ss), EPSF);
}

// ---------------- fused Q / Km / V materialization (one launch, segmented) ----------------
#define QBLK 10368   // NQ*DK/256
#define KBLK 2592    // NL*DK/256
#define VBLK 5184    // DV*NL/256

__global__ void __launch_bounds__(256)
fused_build() {
    uint32_t b = blockIdx.y;
    uint32_t bx = blockIdx.x;
    if (bx < QBLK) {
        uint32_t idx = bx * 256u + threadIdx.x;
        uint32_t d = idx % DK, q = idx / DK;
        uint32_t c = d / 9, kk = d % 9, ky = kk / 3, kx = kk % 3;
        uint32_t y = q / HIMG, x = q % HIMG;
        int yy = (int)(y + ky) - 1, xx = (int)(x + kx) - 1;
        float v = 0.f;
        if (yy >= 0 && yy < HIMG && xx >= 0 && xx < HIMG)
            v = g_match[(size_t)b * (CR * NQ) + (c * HIMG + yy) * HIMG + xx];
        g_Q[(size_t)b * (NQ * DK) + idx] = __float2half_rn(v);
    } else if (bx < QBLK + KBLK) {
        uint32_t idx = (bx - QBLK) * 256u + threadIdx.x;
        uint32_t d = idx % DK, l = idx / DK;
        uint32_t c = d / 9, kk = d % 9, ky = kk / 3, kx = kk % 3;
        uint32_t ly = l / SIMG, lx = l % SIMG;
        int yy = (int)(ly + ky) - 1, xx = (int)(lx + kx) - 1;
        float v = 0.f;
        if (yy >= 0 && yy < SIMG && xx >= 0 && xx < SIMG)
            v = g_ref[(size_t)b * (CR * NL) + (c * SIMG + yy) * SIMG + xx];
        g_Km[(size_t)b * (NL * DK) + idx] = __float2half_rn(v * g_invn[b * NL + l]);
    } else {
        uint32_t idx = (bx - QBLK - KBLK) * 256u + threadIdx.x;
        uint32_t l = idx % NL, dv = idx / NL;
        uint32_t c = dv / 9, kk = dv % 9, ky = kk / 3, kx = kk % 3;
        uint32_t ly = l / SIMG, lx = l % SIMG;
        int yy = (int)(ly + ky) - 1, xx = (int)(lx + kx) - 1;
        float v = 0.f;
        if (yy >= 0 && yy < SIMG && xx >= 0 && xx < SIMG)
            v = g_embed[(size_t)b * (C64 * NL) + (c * SIMG + yy) * SIMG + xx];
        g_V[(size_t)b * (DV * NL) + idx] = __float2half_rn(v);
    }
}

// ---------------- row softmax over 2304 keys: fp32 S -> fp16 P ----------------
__global__ void __launch_bounds__(256)
softmax_rows() {
    const float* p = g_S + (size_t)blockIdx.x * NL;
    __half* po = g_P + (size_t)blockIdx.x * NL;
    const int t = threadIdx.x;
    const int wid = t >> 5, lane = t & 31;
    __shared__ float red[8];

    float v[9];
    float m = -1e30f;
#pragma unroll
    for (int i = 0; i < 9; i++) { v[i] = p[t + i * 256]; m = fmaxf(m, v[i]); }
#pragma unroll
    for (int o = 16; o > 0; o >>= 1) m = fmaxf(m, __shfl_xor_sync(0xffffffffu, m, o));
    if (lane == 0) red[wid] = m;
    __syncthreads();
#pragma unroll
    for (int w = 0; w < 8; w++) m = fmaxf(m, red[w]);

    float sum = 0.f;
#pragma unroll
    for (int i = 0; i < 9; i++) { v[i] = __expf(v[i] - m); sum += v[i]; }
#pragma unroll
    for (int o = 16; o > 0; o >>= 1) sum += __shfl_xor_sync(0xffffffffu, sum, o);
    __syncthreads();
    if (lane == 0) red[wid] = sum;
    __syncthreads();
    sum = 0.f;
#pragma unroll
    for (int w = 0; w < 8; w++) sum += red[w];
    float inv = 1.f / sum;
#pragma unroll
    for (int i = 0; i < 9; i++) po[t + i * 256] = __float2half_rn(v[i] * inv);
}

// ---------------- smem-tiled gather epilogue ----------------
// Block = (2 q-rows y,y+1) x (49 x incl. halo) x (16-channel chunk = 144 dv).
// Load O coalesced (576B runs) into smem with zero-fill at x=96 / y=96, then
// gather the 1/2/4 transposed-conv taps from smem. Writes coalesced along X.
#define EP_SMEM (2 * 49 * 144 * 4)   // 56448 B

__global__ void __launch_bounds__(256)
epilogue(float* __restrict__ out) {
    extern __shared__ float sO[];            // [r][x][dv'] = [(r*49+x)*144+dv']
    const int bx = blockIdx.x;               // 0..1  (X half)
    const int by = blockIdx.y;               // 0..95 (y pair -> Y=2by, 2by+1)
    const int b  = blockIdx.z >> 2;
    const int cc = blockIdx.z & 3;           // 16-channel chunk
    const int tid = threadIdx.x;

    const float* Ob = g_O + (size_t)b * NQ * DV + cc * 144;

    // load: 3528 float4 = 2 rows * 49 x * 36 float4
    for (int i = tid; i < 3528; i += 256) {
        int dv4 = i % 36;
        int rem = i / 36;
        int x = rem % 49, r = rem / 49;
        int y = by + r;
        int xg = 48 * bx + x;
        float4 v = make_float4(0.f, 0.f, 0.f, 0.f);
        if (y < 96 && xg < 96)
            v = *(const float4*)(Ob + (size_t)(y * HIMG + xg) * DV + dv4 * 4);
        *(float4*)(sO + (size_t)i * 4) = v;
    }
    __syncthreads();

    // compute: 96 X * 2 Ypar * 16 c = 3072 outputs
    for (int j = 0; j < 12; j++) {
        int idx = tid + 256 * j;
        int Xl = idx % 96;
        int rem = idx / 96;
        int yp = rem & 1;
        int cp = rem >> 1;
        int X = 96 * bx + Xl;
        int Y = 2 * by + yp;
        if (X >= OHW || Y >= OHW) continue;

        // X taps
        int lx0, kx0, lx1 = -1, kx1 = 0;
        if (Xl & 1) { lx0 = (Xl - 1) >> 1; kx0 = 2; lx1 = (Xl + 1) >> 1; kx1 = 0; }
        else        { lx0 = Xl >> 1;       kx0 = 1; }
        // Y taps: yp==0 -> (r=0, ky=1); yp==1 -> (r=0, ky=2) + (r=1, ky=0)
        const int base9 = cp * 9;
        float sv = 0.f;
        if (yp == 0) {
            const float* row = sO + (size_t)lx0 * 144;
            sv += row[base9 + 3 + kx0];
            if (lx1 >= 0) sv += sO[(size_t)lx1 * 144 + base9 + 3 + kx1];
        } else {
            const float* r0 = sO;                    // r=0, ky=2
            const float* r1 = sO + (size_t)49 * 144; // r=1, ky=0
            sv += r0[(size_t)lx0 * 144 + base9 + 6 + kx0];
            sv += r1[(size_t)lx0 * 144 + base9 + 0 + kx0];
            if (lx1 >= 0) {
                sv += r0[(size_t)lx1 * 144 + base9 + 6 + kx1];
                sv += r1[(size_t)lx1 * 144 + base9 + 0 + kx1];
            }
        }
        out[(((size_t)b * C64 + cc * 16 + cp) * OHW + Y) * OHW + X] = sv * (1.0f / 6.0f);
    }
}

// ---------------- launch ----------------
extern "C" void kernel_launch(void* const* d_in, const int* in_sizes, int n_in,
                              void* d_out, int out_size) {
    const float* input = (const float*)d_in[0];
    const float* small = (const float*)d_in[1];
    const float* w1 = (const float*)d_in[2];
    const float* b1 = (const float*)d_in[3];
    const float* a1 = (const float*)d_in[4];
    const float* w2 = (const float*)d_in[5];
    const float* b2 = (const float*)d_in[6];
    const float* a2 = (const float*)d_in[7];
    const float* wa = (const float*)d_in[8];
    const float* ba = (const float*)d_in[9];
    const float* aa = (const float*)d_in[10];
    float* out = (float*)d_out;

    float *p_match, *p_embed, *p_ref, *p_S, *p_O;
    __half *p_Q, *p_Km, *p_V, *p_P;
    cudaGetSymbolAddress((void**)&p_match, g_match);
    cudaGetSymbolAddress((void**)&p_embed, g_embed);
    cudaGetSymbolAddress((void**)&p_ref,   g_ref);
    cudaGetSymbolAddress((void**)&p_Q,     g_Q);
    cudaGetSymbolAddress((void**)&p_Km,    g_Km);
    cudaGetSymbolAddress((void**)&p_V,     g_V);
    cudaGetSymbolAddress((void**)&p_S,     g_S);
    cudaGetSymbolAddress((void**)&p_P,     g_P);
    cudaGetSymbolAddress((void**)&p_O,     g_O);

    cudaFuncSetAttribute(gemm_f16<128>, cudaFuncAttributeMaxDynamicSharedMemorySize, G1_SMEM);
    cudaFuncSetAttribute(gemm_f16<192>, cudaFuncAttributeMaxDynamicSharedMemorySize, G2_SMEM);
    cudaFuncSetAttribute(epilogue, cudaFuncAttributeMaxDynamicSharedMemorySize, EP_SMEM);

    // #0: all three feature maps
    fused_convs<<<dim3(144, 3), 256>>>(input, small, w1, b1, a1, w2, b2, a2, wa, ba, aa,
                                       p_match, p_embed, p_ref);
    // #1: key norms
    key_inv_norms<<<36, 256>>>();
    // #2: Q / Km / V (fp16)
    fused_build<<<dim3(QBLK + KBLK + VBLK, BATCH), 256>>>();
    // #3: S = 10 * Q Km^T   <-- ncu capture target
    gemm_f16<128><<<dim3(18, 72, BATCH), 256, G1_SMEM>>>(
        p_Q, p_Km, p_S, DK, NL, SCALEF,
        (size_t)NQ * DK, (size_t)NL * DK, (size_t)NQ * NL);
    // #4: softmax -> fp16 P
    softmax_rows<<<BATCH * NQ, 256>>>();
    // #5: O = P V
    gemm_f16<192><<<dim3(3, 72, BATCH), 384, G2_SMEM>>>(
        p_P, p_V, p_O, NL, DV, 1.0f,
        (size_t)NQ * NL, (size_t)DV * NL, (size_t)NQ * DV);
    // #6: smem-tiled gather into [4,64,191,191] with /6
    epilogue<<<dim3(2, 96, 4 * BATCH), 256, EP_SMEM>>>(out);
}

// round 17
// speedup vs baseline: 1.1241x; 1.0856x over previous
#include <cuda_runtime.h>
#include <cuda_fp16.h>
#include <cstdint>
#include <math.h>

#define BATCH 4
#define C64   64
#define CR    32
#define HIMG  96
#define SIMG  48
#define NQ    9216      // 96*96 queries
#define NL    2304      // 48*48 keys
#define DK    288       // 32*3*3
#define DV    576       // 64*3*3
#define OHW   191
#define SCALEF 10.0f
#define EPSF   1e-4f

// ---------------- scratch (device globals; no allocation allowed) ----------------
__device__ float  g_match[(size_t)BATCH * CR  * NQ];
__device__ float  g_embed[(size_t)BATCH * C64 * NL];
__device__ float  g_ref  [(size_t)BATCH * CR  * NL];
__device__ __half g_Q    [(size_t)BATCH * NQ  * DK];
__device__ __half g_Km   [(size_t)BATCH * NL  * DK];
__device__ __half g_V    [(size_t)BATCH * DV  * NL];
__device__ float  g_invn [(size_t)BATCH * NL];
__device__ float  g_S    [(size_t)BATCH * NQ  * NL];   // fp32 logits
__device__ __half g_P    [(size_t)BATCH * NQ  * NL];   // fp16 probs
__device__ float  g_O    [(size_t)BATCH * NQ  * DV];

// ==================== FP16 tensor-core GEMM ====================
// C[M,Nb] = alpha * A[M,K] * B[Nb,K]^T ; A,B fp16 K-contig, C fp32.
// Block tile 128 x NT, NT/16 warps (4m x NT/64 n) each 32x64.
// K-tile KT (32 or 64), 3-stage cp.async, one __syncthreads per K-tile.
// GEMM1: NT=128, KT=32 (proven r14 config, byte-identical addressing W=80).
// GEMM2: NT=192, KT=64 (halves barrier count over K=2304).
// REQUIRES: M % 128 == 0, Nb % NT == 0, K % KT == 0 (no guards anywhere).
// Row stride W = KT*2+16 B -> ldmatrix 8-row phases hit banks (W/4*r+4c)%32,
// = 20r%32 (W=80) or (36r+4c)%32 (W=144): all 8 distinct either way.

__device__ __forceinline__ void mma_f16(float c[4], const uint32_t a[4], const uint32_t b[2]) {
    asm volatile(
        "mma.sync.aligned.m16n8k16.row.col.f32.f16.f16.f32 "
        "{%0,%1,%2,%3}, {%4,%5,%6,%7}, {%8,%9}, {%0,%1,%2,%3};"
        : "+f"(c[0]), "+f"(c[1]), "+f"(c[2]), "+f"(c[3])
        : "r"(a[0]), "r"(a[1]), "r"(a[2]), "r"(a[3]), "r"(b[0]), "r"(b[1]));
}

#define LDSM_X4(r0, r1, r2, r3, addr) \
    asm volatile("ldmatrix.sync.aligned.m8n8.x4.shared.b16 {%0,%1,%2,%3}, [%4];" \
                 : "=r"(r0), "=r"(r1), "=r"(r2), "=r"(r3) : "r"(addr))

__device__ __forceinline__ void cp16(uint32_t dst, const void* src) {
    asm volatile("cp.async.cg.shared.global [%0], [%1], 16;" :: "r"(dst), "l"(src));
}

template<int NT, int KT>
__global__ void __launch_bounds__(NT * 2, 256 / NT)
gemm_f16(const __half* __restrict__ A, const __half* __restrict__ B, float* __restrict__ C,
         int K, int Nb, float alpha, size_t sA, size_t sB, size_t sC) {
    constexpr int NTHR   = NT * 2;
    constexpr int W      = KT * 2 + 16;       // row stride bytes (80 or 144)
    constexpr int ROWB   = KT / 8;            // 16B chunks per row (4 or 8)
    constexpr int A_ST   = 128 * W;
    constexpr int STAGE  = (128 + NT) * W;
    constexpr int A_CH   = 128 * ROWB;
    constexpr int TOT_CH = (128 + NT) * ROWB;
    constexpr int KS_N   = KT / 16;           // mma k-steps per K-tile (2 or 4)

    extern __shared__ __align__(16) char smc[];
    const uint32_t smem_u = (uint32_t)__cvta_generic_to_shared(smc);

    const int tid = threadIdx.x;
    const int warp = tid >> 5, lane = tid & 31;
    const int g = lane >> 2, t = lane & 3;
    const int wm = warp & 3, wn = warp >> 2;
    const int m0 = blockIdx.y * 128, n0 = blockIdx.x * NT;
    const __half* Ab = A + (size_t)blockIdx.z * sA;
    const __half* Bb = B + (size_t)blockIdx.z * sB;
    float* Cb = C + (size_t)blockIdx.z * sC;

    float acc[2][8][4];
#pragma unroll
    for (int i = 0; i < 2; i++)
#pragma unroll
        for (int j = 0; j < 8; j++)
#pragma unroll
            for (int r = 0; r < 4; r++) acc[i][j][r] = 0.f;

    auto ld_stage = [&](int c, int s) {
        const int k0 = c * KT;
        const uint32_t sb = smem_u + (uint32_t)s * STAGE;
#pragma unroll
        for (int i = 0; i < (TOT_CH + NTHR - 1) / NTHR; i++) {
            int ch = tid + NTHR * i;
            if (ch < A_CH) {
                int row = ch / ROWB, c16 = ch % ROWB;
                cp16(sb + row * W + c16 * 16,
                     Ab + (size_t)(m0 + row) * K + k0 + c16 * 8);
            } else if (ch < TOT_CH) {
                int bc = ch - A_CH;
                int row = bc / ROWB, c16 = bc % ROWB;
                cp16(sb + A_ST + row * W + c16 * 16,
                     Bb + (size_t)(n0 + row) * K + k0 + c16 * 8);
            }
        }
        asm volatile("cp.async.commit_group;" ::: "memory");
    };

    const int nk = K / KT;
    ld_stage(0, 0);
    if (nk > 1) ld_stage(1, 1);

    // ldmatrix lane addressing (fragment maps validated rounds 4-16)
    const uint32_t a_row = (uint32_t)(wm * 32 + (lane & 15));
    const uint32_t a_chk = (uint32_t)(lane >> 4);
    const uint32_t b_row = (uint32_t)(wn * 64 + (lane & 7) + ((lane & 16) >> 1));
    const uint32_t b_chk = (uint32_t)((lane >> 3) & 1);

    int s = 0, ps = 2;
    for (int kt = 0; kt < nk; kt++) {
        // pending groups: loads kt, kt+1. wait 1 drains kt; last iter drains all.
        if (kt + 1 < nk) asm volatile("cp.async.wait_group 1;" ::: "memory");
        else             asm volatile("cp.async.wait_group 0;" ::: "memory");
        __syncthreads();
        if (kt + 2 < nk) {
            ld_stage(kt + 2, ps);
            ps = (ps == 2) ? 0 : ps + 1;
        }
        const uint32_t As = smem_u + (uint32_t)s * STAGE;
        const uint32_t Bs = As + A_ST;
#pragma unroll
        for (int ks = 0; ks < KS_N; ks++) {
            uint32_t afr[2][4], bfr[8][2];
#pragma unroll
            for (int mi = 0; mi < 2; mi++) {
                uint32_t ad = As + (a_row + mi * 16) * W + (a_chk + ks * 2) * 16;
                LDSM_X4(afr[mi][0], afr[mi][1], afr[mi][2], afr[mi][3], ad);
            }
#pragma unroll
            for (int a = 0; a < 4; a++) {
                uint32_t bd = Bs + (b_row + a * 16) * W + (b_chk + ks * 2) * 16;
                LDSM_X4(bfr[2 * a][0], bfr[2 * a][1], bfr[2 * a + 1][0], bfr[2 * a + 1][1], bd);
            }
#pragma unroll
            for (int mi = 0; mi < 2; mi++)
#pragma unroll
                for (int ni = 0; ni < 8; ni++)
                    mma_f16(acc[mi][ni], afr[mi], bfr[ni]);
        }
        s = (s == 2) ? 0 : s + 1;
    }

    // epilogue (no guards: exact tiling)
#pragma unroll
    for (int mi = 0; mi < 2; mi++) {
        int row0 = m0 + wm * 32 + mi * 16 + g;
#pragma unroll
        for (int ni = 0; ni < 8; ni++) {
            int col = n0 + wn * 64 + ni * 8 + 2 * t;
            *(float2*)(Cb + (size_t)row0 * Nb + col) =
                make_float2(acc[mi][ni][0] * alpha, acc[mi][ni][1] * alpha);
            *(float2*)(Cb + (size_t)(row0 + 8) * Nb + col) =
                make_float2(acc[mi][ni][2] * alpha, acc[mi][ni][3] * alpha);
        }
    }
}

#define G1_SMEM (3 * (128 + 128) * 80)    // 61440  (NT=128, KT=32)
#define G2_SMEM (3 * (128 + 192) * 144)   // 138240 (NT=192, KT=64)

// ---------------- fused 1x1 convs + PReLU (one launch, 3 segments) ----------------
template<int COUT>
__device__ __forceinline__ void conv_body(const float* __restrict__ in,
                                          const float* __restrict__ w,
                                          const float* __restrict__ bias,
                                          const float* __restrict__ a,
                                          float* __restrict__ out, int HW, float* ws) {
    for (int i = threadIdx.x; i < COUT * C64; i += 256) ws[i] = w[i];
    __syncthreads();
    const float alpha = a[0];
    int idx = blockIdx.x * 256 + threadIdx.x;
    int b = idx / HW, p = idx - b * HW;
    const float* inp = in + (size_t)b * C64 * HW + p;
    float acc[COUT];
#pragma unroll
    for (int o = 0; o < COUT; o++) acc[o] = bias[o];
    for (int c = 0; c < C64; c++) {
        float v = inp[(size_t)c * HW];
#pragma unroll
        for (int o = 0; o < COUT; o++) acc[o] = fmaf(ws[o * C64 + c], v, acc[o]);
    }
    float* op = out + (size_t)b * COUT * HW + p;
#pragma unroll
    for (int o = 0; o < COUT; o++) {
        float v = acc[o];
        op[(size_t)o * HW] = (v >= 0.f) ? v : alpha * v;
    }
}

__global__ void __launch_bounds__(256)
fused_convs(const float* __restrict__ input, const float* __restrict__ small,
            const float* __restrict__ w1, const float* __restrict__ b1, const float* __restrict__ a1,
            const float* __restrict__ w2, const float* __restrict__ b2, const float* __restrict__ a2,
            const float* __restrict__ wa, const float* __restrict__ ba, const float* __restrict__ aa,
            float* __restrict__ pm, float* __restrict__ pe, float* __restrict__ pr) {
    __shared__ float ws[C64 * C64];
    if (blockIdx.y == 0) {
        conv_body<CR>(input, w1, b1, a1, pm, NQ, ws);
    } else if (blockIdx.y == 1) {
        if (blockIdx.x >= 36) return;
        conv_body<C64>(small, wa, ba, aa, pe, NL, ws);
    } else {
        if (blockIdx.x >= 36) return;
        conv_body<CR>(small, w2, b2, a2, pr, NL, ws);
    }
}

// ---------------- per-key inverse patch norms ----------------
__global__ void key_inv_norms() {
    int idx = blockIdx.x * 256 + threadIdx.x;
    int l = idx % NL, b = idx / NL;
    int ly = l / SIMG, lx = l % SIMG;
    const float* rb = g_ref + (size_t)b * CR * NL;
    float ss = 0.f;
    for (int c = 0; c < CR; c++)
        for (int ky = 0; ky < 3; ky++) {
            int yy = ly + ky - 1;
            if (yy < 0 || yy >= SIMG) continue;
            for (int kx = 0; kx < 3; kx++) {
                int xx = lx + kx - 1;
                if (xx < 0 || xx >= SIMG) continue;
                float v = rb[(c * SIMG + yy) * SIMG + xx];
                ss += v * v;
            }
        }
    g_invn[idx] = 1.f / fmaxf(sqrtf(ss), EPSF);
}

// ---------------- fused Q / Km / V materialization (one launch, segmented) ----------------
#define QBLK 10368   // NQ*DK/256
#define KBLK 2592    // NL*DK/256
#define VBLK 5184    // DV*NL/256

__global__ void __launch_bounds__(256)
fused_build() {
    uint32_t b = blockIdx.y;
    uint32_t bx = blockIdx.x;
    if (bx < QBLK) {
        uint32_t idx = bx * 256u + threadIdx.x;
        uint32_t d = idx % DK, q = idx / DK;
        uint32_t c = d / 9, kk = d % 9, ky = kk / 3, kx = kk % 3;
        uint32_t y = q / HIMG, x = q % HIMG;
        int yy = (int)(y + ky) - 1, xx = (int)(x + kx) - 1;
        float v = 0.f;
        if (yy >= 0 && yy < HIMG && xx >= 0 && xx < HIMG)
            v = g_match[(size_t)b * (CR * NQ) + (c * HIMG + yy) * HIMG + xx];
        g_Q[(size_t)b * (NQ * DK) + idx] = __float2half_rn(v);
    } else if (bx < QBLK + KBLK) {
        uint32_t idx = (bx - QBLK) * 256u + threadIdx.x;
        uint32_t d = idx % DK, l = idx / DK;
        uint32_t c = d / 9, kk = d % 9, ky = kk / 3, kx = kk % 3;
        uint32_t ly = l / SIMG, lx = l % SIMG;
        int yy = (int)(ly + ky) - 1, xx = (int)(lx + kx) - 1;
        float v = 0.f;
        if (yy >= 0 && yy < SIMG && xx >= 0 && xx < SIMG)
            v = g_ref[(size_t)b * (CR * NL) + (c * SIMG + yy) * SIMG + xx];
        g_Km[(size_t)b * (NL * DK) + idx] = __float2half_rn(v * g_invn[b * NL + l]);
    } else {
        uint32_t idx = (bx - QBLK - KBLK) * 256u + threadIdx.x;
        uint32_t l = idx % NL, dv = idx / NL;
        uint32_t c = dv / 9, kk = dv % 9, ky = kk / 3, kx = kk % 3;
        uint32_t ly = l / SIMG, lx = l % SIMG;
        int yy = (int)(ly + ky) - 1, xx = (int)(lx + kx) - 1;
        float v = 0.f;
        if (yy >= 0 && yy < SIMG && xx >= 0 && xx < SIMG)
            v = g_embed[(size_t)b * (C64 * NL) + (c * SIMG + yy) * SIMG + xx];
        g_V[(size_t)b * (DV * NL) + idx] = __float2half_rn(v);
    }
}

// ---------------- row softmax over 2304 keys: fp32 S -> fp16 P ----------------
__global__ void __launch_bounds__(256)
softmax_rows() {
    const float* p = g_S + (size_t)blockIdx.x * NL;
    __half* po = g_P + (size_t)blockIdx.x * NL;
    const int t = threadIdx.x;
    const int wid = t >> 5, lane = t & 31;
    __shared__ float red[8];

    float v[9];
    float m = -1e30f;
#pragma unroll
    for (int i = 0; i < 9; i++) { v[i] = p[t + i * 256]; m = fmaxf(m, v[i]); }
#pragma unroll
    for (int o = 16; o > 0; o >>= 1) m = fmaxf(m, __shfl_xor_sync(0xffffffffu, m, o));
    if (lane == 0) red[wid] = m;
    __syncthreads();
#pragma unroll
    for (int w = 0; w < 8; w++) m = fmaxf(m, red[w]);

    float sum = 0.f;
#pragma unroll
    for (int i = 0; i < 9; i++) { v[i] = __expf(v[i] - m); sum += v[i]; }
#pragma unroll
    for (int o = 16; o > 0; o >>= 1) sum += __shfl_xor_sync(0xffffffffu, sum, o);
    __syncthreads();
    if (lane == 0) red[wid] = sum;
    __syncthreads();
    sum = 0.f;
#pragma unroll
    for (int w = 0; w < 8; w++) sum += red[w];
    float inv = 1.f / sum;
#pragma unroll
    for (int i = 0; i < 9; i++) po[t + i * 256] = __float2half_rn(v[i] * inv);
}

// ---------------- gather epilogue (r14 simple form — L2-friendly) ----------------
__global__ void __launch_bounds__(256)
epilogue(float* __restrict__ out) {
    uint32_t idx = blockIdx.x * 256u + threadIdx.x;   // per-batch C64*OHW*OHW
    uint32_t b = blockIdx.y;
    if (idx >= (uint32_t)C64 * OHW * OHW) return;
    uint32_t X = idx % OHW;
    uint32_t r = idx / OHW;
    uint32_t Y = r % OHW;
    uint32_t c = r / OHW;

    int ys[2], kys[2], ny;
    if (Y & 1) { ny = 2; ys[0] = (Y - 1) >> 1; kys[0] = 2; ys[1] = (Y + 1) >> 1; kys[1] = 0; }
    else       { ny = 1; ys[0] = Y >> 1;       kys[0] = 1; }
    int xs[2], kxs[2], nx;
    if (X & 1) { nx = 2; xs[0] = (X - 1) >> 1; kxs[0] = 2; xs[1] = (X + 1) >> 1; kxs[1] = 0; }
    else       { nx = 1; xs[0] = X >> 1;       kxs[0] = 1; }

    const float* Ob = g_O + (size_t)b * NQ * DV;
    float sv = 0.f;
    for (int iy = 0; iy < ny; iy++)
        for (int ix = 0; ix < nx; ix++) {
            uint32_t q = ys[iy] * HIMG + xs[ix];
            sv += Ob[q * DV + c * 9 + kys[iy] * 3 + kxs[ix]];
        }
    out[(size_t)b * (C64 * OHW * OHW) + idx] = sv * (1.0f / 6.0f);
}

// ---------------- launch ----------------
extern "C" void kernel_launch(void* const* d_in, const int* in_sizes, int n_in,
                              void* d_out, int out_size) {
    const float* input = (const float*)d_in[0];
    const float* small = (const float*)d_in[1];
    const float* w1 = (const float*)d_in[2];
    const float* b1 = (const float*)d_in[3];
    const float* a1 = (const float*)d_in[4];
    const float* w2 = (const float*)d_in[5];
    const float* b2 = (const float*)d_in[6];
    const float* a2 = (const float*)d_in[7];
    const float* wa = (const float*)d_in[8];
    const float* ba = (const float*)d_in[9];
    const float* aa = (const float*)d_in[10];
    float* out = (float*)d_out;

    float *p_match, *p_embed, *p_ref, *p_S, *p_O;
    __half *p_Q, *p_Km, *p_V, *p_P;
    cudaGetSymbolAddress((void**)&p_match, g_match);
    cudaGetSymbolAddress((void**)&p_embed, g_embed);
    cudaGetSymbolAddress((void**)&p_ref,   g_ref);
    cudaGetSymbolAddress((void**)&p_Q,     g_Q);
    cudaGetSymbolAddress((void**)&p_Km,    g_Km);
    cudaGetSymbolAddress((void**)&p_V,     g_V);
    cudaGetSymbolAddress((void**)&p_S,     g_S);
    cudaGetSymbolAddress((void**)&p_P,     g_P);
    cudaGetSymbolAddress((void**)&p_O,     g_O);

    cudaFuncSetAttribute((const void*)gemm_f16<128, 32>,
                         cudaFuncAttributeMaxDynamicSharedMemorySize, G1_SMEM);
    cudaFuncSetAttribute((const void*)gemm_f16<192, 64>,
                         cudaFuncAttributeMaxDynamicSharedMemorySize, G2_SMEM);

    // #0: all three feature maps
    fused_convs<<<dim3(144, 3), 256>>>(input, small, w1, b1, a1, w2, b2, a2, wa, ba, aa,
                                       p_match, p_embed, p_ref);
    // #1: key norms
    key_inv_norms<<<36, 256>>>();
    // #2: Q / Km / V (fp16)
    fused_build<<<dim3(QBLK + KBLK + VBLK, BATCH), 256>>>();
    // #3: S = 10 * Q Km^T   <-- ncu capture target
    gemm_f16<128, 32><<<dim3(18, 72, BATCH), 256, G1_SMEM>>>(
        p_Q, p_Km, p_S, DK, NL, SCALEF,
        (size_t)NQ * DK, (size_t)NL * DK, (size_t)NQ * NL);
    // #4: softmax -> fp16 P
    softmax_rows<<<BATCH * NQ, 256>>>();
    // #5: O = P V  (KT=64: 36 K-iterations instead of 72)
    gemm_f16<192, 64><<<dim3(3, 72, BATCH), 384, G2_SMEM>>>(
        p_P, p_V, p_O, NL, DV, 1.0f,
        (size_t)NQ * NL, (size_t)DV * NL, (size_t)NQ * DV);
    // #6: gather into [4,64,191,191] with /6
    epilogue<<<dim3(9121, BATCH), 256>>>(out);
}